// round 7
// baseline (speedup 1.0000x reference)
#include <cuda_runtime.h>
#include <cuda_bf16.h>
#include <cstdint>

// GCN: out = spmm(A, relu(spmm(A, x@W1)+b1) @ W2) + b2
// N=50000, E=1.6M, 512 -> 128 -> 64.
// GEMMs: mma.sync tf32 (rn-rounded). SpMM: on-device CSR build + warp-per-row.
// edge_index is int32 on device (JAX default config downcasts int64).

#define IN_DIM  512
#define HID_DIM 128
#define OUT_DIM 64
#define N_MAX   50000
#define E_MAX   1600000

__device__ float g_S1[(size_t)N_MAX * HID_DIM];  // x @ W1
__device__ float g_H [(size_t)N_MAX * HID_DIM];  // spmm1 out (+b1)
__device__ float g_S2[(size_t)N_MAX * OUT_DIM];  // relu(H) @ W2

// CSR scratch
__device__ int  g_rowptr[N_MAX + 1];
__device__ int  g_rowaux[N_MAX];      // counts, then scatter cursors
__device__ int2 g_edges [E_MAX];      // {colidx, weight-as-int}

// ---------------------------------------------------------------------------
__device__ __forceinline__ float to_tf32_rn(float f) {
    uint32_t o;
    asm("cvt.rn.tf32.f32 %0, %1;" : "=r"(o) : "f"(f));
    return __uint_as_float(o);
}

// ---------------------------------------------------------------------------
// tf32 mma GEMM: C[M,BN] = op(A)[M,K] @ W[K,BN]. op = ReLU if RELU.
// Block tile 128 x BN, BK=32. 8 warps: 4 along M x 2 along N.
// Warp tile 32 x BN/2; NT = BN/16 mma n-tiles per warp.
// ---------------------------------------------------------------------------
template<int BN, int K, bool RELU>
__global__ __launch_bounds__(256) void gemm_mma_tf32(
        const float* __restrict__ A, const float* __restrict__ W,
        float* __restrict__ C, int M) {
    constexpr int BM = 128, BK = 32, LDA = 36;
    constexpr int NT = BN / 16;
    __shared__ float sA[BM * LDA];   // row-major [m][k], padded
    __shared__ float sB[BN * LDA];   // TRANSPOSED [n][k], padded

    const int tid  = threadIdx.x;
    const int wid  = tid >> 5;
    const int lane = tid & 31;
    const int gid  = lane >> 2;      // 0..7
    const int tig  = lane & 3;       // 0..3
    const int warpM = (wid & 3) * 32;
    const int warpN = (wid >> 2) * (BN / 2);
    const int rowBase = blockIdx.x * BM;

    float acc[2][NT][4];
    #pragma unroll
    for (int a = 0; a < 2; a++)
        #pragma unroll
        for (int b = 0; b < NT; b++)
            #pragma unroll
            for (int c = 0; c < 4; c++) acc[a][b][c] = 0.f;

    for (int k0 = 0; k0 < K; k0 += BK) {
        // A tile: 128 x 32 floats (rn-rounded to tf32, optional ReLU)
        #pragma unroll
        for (int i = 0; i < 4; i++) {
            int f = tid + i * 256;
            int r = f >> 3, q = f & 7;
            int m = rowBase + r;
            float4 v = make_float4(0.f, 0.f, 0.f, 0.f);
            if (m < M) v = *(const float4*)(A + (size_t)m * K + k0 + q * 4);
            if (RELU) {
                v.x = fmaxf(v.x, 0.f); v.y = fmaxf(v.y, 0.f);
                v.z = fmaxf(v.z, 0.f); v.w = fmaxf(v.w, 0.f);
            }
            v.x = to_tf32_rn(v.x); v.y = to_tf32_rn(v.y);
            v.z = to_tf32_rn(v.z); v.w = to_tf32_rn(v.w);
            *(float4*)&sA[r * LDA + q * 4] = v;
        }
        // B tile transposed: sB[n][kl] = W[k0+kl][n]
        #pragma unroll
        for (int i = 0; i < BK * BN / 256; i++) {
            int f = tid + i * 256;
            int kl = f / BN, n = f % BN;
            sB[n * LDA + kl] = to_tf32_rn(W[(size_t)(k0 + kl) * BN + n]);
        }
        __syncthreads();

        #pragma unroll
        for (int kk = 0; kk < 4; kk++) {
            const int k = kk * 8;
            uint32_t bf[NT][2];
            #pragma unroll
            for (int nt = 0; nt < NT; nt++) {
                int n = warpN + nt * 8 + gid;
                bf[nt][0] = __float_as_uint(sB[n * LDA + k + tig]);
                bf[nt][1] = __float_as_uint(sB[n * LDA + k + 4 + tig]);
            }
            #pragma unroll
            for (int mt = 0; mt < 2; mt++) {
                int r0 = warpM + mt * 16 + gid;
                uint32_t a0 = __float_as_uint(sA[r0 * LDA + k + tig]);
                uint32_t a1 = __float_as_uint(sA[(r0 + 8) * LDA + k + tig]);
                uint32_t a2 = __float_as_uint(sA[r0 * LDA + k + 4 + tig]);
                uint32_t a3 = __float_as_uint(sA[(r0 + 8) * LDA + k + 4 + tig]);
                #pragma unroll
                for (int nt = 0; nt < NT; nt++) {
                    asm volatile(
                        "mma.sync.aligned.m16n8k8.row.col.f32.tf32.tf32.f32 "
                        "{%0,%1,%2,%3}, {%4,%5,%6,%7}, {%8,%9}, {%0,%1,%2,%3};"
                        : "+f"(acc[mt][nt][0]), "+f"(acc[mt][nt][1]),
                          "+f"(acc[mt][nt][2]), "+f"(acc[mt][nt][3])
                        : "r"(a0), "r"(a1), "r"(a2), "r"(a3),
                          "r"(bf[nt][0]), "r"(bf[nt][1]));
                }
            }
        }
        __syncthreads();
    }

    #pragma unroll
    for (int mt = 0; mt < 2; mt++) {
        #pragma unroll
        for (int rr = 0; rr < 2; rr++) {
            int m = rowBase + warpM + mt * 16 + rr * 8 + gid;
            if (m < M) {
                float* cp = C + (size_t)m * BN + warpN;
                #pragma unroll
                for (int nt = 0; nt < NT; nt++) {
                    *(float2*)(cp + nt * 8 + 2 * tig) =
                        make_float2(acc[mt][nt][rr * 2 + 0], acc[mt][nt][rr * 2 + 1]);
                }
            }
        }
    }
}

// ---------------------------------------------------------------------------
// CSR build
// ---------------------------------------------------------------------------
__global__ void zero_counts_kernel(int* __restrict__ cnt, int n) {
    int i = blockIdx.x * blockDim.x + threadIdx.x;
    if (i < n) cnt[i] = 0;
}

__global__ void hist_kernel(const int* __restrict__ rows, int* __restrict__ cnt, int E) {
    int e = blockIdx.x * blockDim.x + threadIdx.x;
    if (e < E) atomicAdd(&cnt[rows[e]], 1);
}

// Single-block exclusive scan over N counts (chunk-per-thread + block scan).
__global__ __launch_bounds__(1024) void scan_kernel(
        int* __restrict__ cnt_and_cursor,   // in: counts, out: cursors (=offsets)
        int* __restrict__ rowptr, int N, int E) {
    __shared__ int part[1024];
    const int t = threadIdx.x;
    const int chunk = (N + 1023) / 1024;
    const int lo = t * chunk;
    const int hi = min(lo + chunk, N);
    int s = 0;
    for (int i = lo; i < hi; i++) s += cnt_and_cursor[i];
    part[t] = s;
    __syncthreads();
    #pragma unroll
    for (int off = 1; off < 1024; off <<= 1) {
        int v = (t >= off) ? part[t - off] : 0;
        __syncthreads();
        part[t] += v;
        __syncthreads();
    }
    int base = (t == 0) ? 0 : part[t - 1];
    for (int i = lo; i < hi; i++) {
        int c = cnt_and_cursor[i];
        rowptr[i] = base;
        cnt_and_cursor[i] = base;   // scatter cursor
        base += c;
    }
    if (t == 0) rowptr[N] = E;
}

__global__ void scatter_kernel(const int* __restrict__ rows,
                               const int* __restrict__ cols,
                               const float* __restrict__ ew,
                               int* __restrict__ cursor,
                               int2* __restrict__ edges, int E) {
    int e = blockIdx.x * blockDim.x + threadIdx.x;
    if (e >= E) return;
    int r = rows[e];
    int pos = atomicAdd(&cursor[r], 1);
    edges[pos] = make_int2(cols[e], __float_as_int(ew[e]));
}

// ---------------------------------------------------------------------------
// CSR SpMM: warp per row, VEC floats per lane (D = 32*VEC).
// dst[row] = bias + sum_j w[j] * src[col[j]]
// ---------------------------------------------------------------------------
template<int VEC>
__global__ void csr_spmm_kernel(const int* __restrict__ rowptr,
                                const int2* __restrict__ edges,
                                const float* __restrict__ src,
                                const float* __restrict__ bias,
                                float* __restrict__ dst, int N) {
    constexpr int D = VEC * 32;
    const int lane = threadIdx.x & 31;
    const int row  = blockIdx.x * (blockDim.x >> 5) + (threadIdx.x >> 5);
    if (row >= N) return;

    const int s = rowptr[row];
    const int e = rowptr[row + 1];

    float acc[VEC];
    #pragma unroll
    for (int v = 0; v < VEC; v++) acc[v] = bias[lane * VEC + v];

    int j = s;
    for (; j + 2 <= e; j += 2) {
        int2 e0 = edges[j], e1 = edges[j + 1];
        float w0 = __int_as_float(e0.y), w1 = __int_as_float(e1.y);
        const float* p0 = src + (size_t)e0.x * D + lane * VEC;
        const float* p1 = src + (size_t)e1.x * D + lane * VEC;
        if (VEC == 4) {
            float4 v0 = *(const float4*)p0;
            float4 v1 = *(const float4*)p1;
            acc[0] = fmaf(w0, v0.x, fmaf(w1, v1.x, acc[0]));
            acc[1] = fmaf(w0, v0.y, fmaf(w1, v1.y, acc[1]));
            acc[2] = fmaf(w0, v0.z, fmaf(w1, v1.z, acc[2]));
            acc[3] = fmaf(w0, v0.w, fmaf(w1, v1.w, acc[3]));
        } else {
            float2 v0 = *(const float2*)p0;
            float2 v1 = *(const float2*)p1;
            acc[0] = fmaf(w0, v0.x, fmaf(w1, v1.x, acc[0]));
            acc[1] = fmaf(w0, v0.y, fmaf(w1, v1.y, acc[1]));
        }
    }
    if (j < e) {
        int2 e0 = edges[j];
        float w0 = __int_as_float(e0.y);
        const float* p0 = src + (size_t)e0.x * D + lane * VEC;
        if (VEC == 4) {
            float4 v0 = *(const float4*)p0;
            acc[0] = fmaf(w0, v0.x, acc[0]);
            acc[1] = fmaf(w0, v0.y, acc[1]);
            acc[2] = fmaf(w0, v0.z, acc[2]);
            acc[3] = fmaf(w0, v0.w, acc[3]);
        } else {
            float2 v0 = *(const float2*)p0;
            acc[0] = fmaf(w0, v0.x, acc[0]);
            acc[1] = fmaf(w0, v0.y, acc[1]);
        }
    }

    float* dp = dst + (size_t)row * D + lane * VEC;
    if (VEC == 4)
        *(float4*)dp = make_float4(acc[0], acc[1], acc[2], acc[3]);
    else
        *(float2*)dp = make_float2(acc[0], acc[1]);
}

// ---------------------------------------------------------------------------
extern "C" void kernel_launch(void* const* d_in, const int* in_sizes, int n_in,
                              void* d_out, int out_size) {
    const float* x  = (const float*)d_in[0];
    const int*   ei = (const int*)d_in[1];     // [2, E] int32
    const float* ew = (const float*)d_in[2];
    const float* W1 = (const float*)d_in[3];
    const float* b1 = (const float*)d_in[4];
    const float* W2 = (const float*)d_in[5];
    const float* b2 = (const float*)d_in[6];
    float* out = (float*)d_out;

    const int M = in_sizes[0] / IN_DIM;   // 50000
    const int E = in_sizes[2];            // 1600000

    float *S1, *H, *S2;
    int *rowptr, *rowaux;
    int2 *edges;
    cudaGetSymbolAddress((void**)&S1, g_S1);
    cudaGetSymbolAddress((void**)&H,  g_H);
    cudaGetSymbolAddress((void**)&S2, g_S2);
    cudaGetSymbolAddress((void**)&rowptr, g_rowptr);
    cudaGetSymbolAddress((void**)&rowaux, g_rowaux);
    cudaGetSymbolAddress((void**)&edges,  g_edges);

    const int* e_rows = ei;
    const int* e_cols = ei + E;

    // --- CSR build (shared by both spmms) ---
    zero_counts_kernel<<<(M + 255) / 256, 256>>>(rowaux, M);
    hist_kernel<<<(E + 255) / 256, 256>>>(e_rows, rowaux, E);
    scan_kernel<<<1, 1024>>>(rowaux, rowptr, M, E);
    scatter_kernel<<<(E + 255) / 256, 256>>>(e_rows, e_cols, ew, rowaux, edges, E);

    // --- GEMM1: S1 = x @ W1 (tf32 mma) ---
    gemm_mma_tf32<HID_DIM, IN_DIM, false><<<(M + 127) / 128, 256>>>(x, W1, S1, M);

    // --- SpMM1: H = A @ S1 + b1 ---
    csr_spmm_kernel<4><<<(M + 7) / 8, 256>>>(rowptr, edges, S1, b1, H, M);

    // --- GEMM2: S2 = relu(H) @ W2 (tf32 mma) ---
    gemm_mma_tf32<OUT_DIM, HID_DIM, true><<<(M + 127) / 128, 256>>>(H, W2, S2, M);

    // --- SpMM2: out = A @ S2 + b2 ---
    csr_spmm_kernel<2><<<(M + 7) / 8, 256>>>(rowptr, edges, S2, b2, out, M);
}

// round 8
// speedup vs baseline: 1.2990x; 1.2990x over previous
#include <cuda_runtime.h>
#include <cuda_bf16.h>
#include <cstdint>

// GCN: out = spmm(A, relu(spmm(A, x@W1)+b1) @ W2) + b2
// N=50000, E=1.6M, 512 -> 128 -> 64.
// GEMM1: mma.sync tf32 (rn). GEMM2: fp32 FFMA (reverted for bisect).
// SpMM: on-device CSR build (int2 {col,w} edges) + warp-per-row.
// edge_index is int32 on device (JAX default config downcasts int64).

#define IN_DIM  512
#define HID_DIM 128
#define OUT_DIM 64
#define N_MAX   50000
#define E_MAX   1600000

__device__ float g_S1[(size_t)N_MAX * HID_DIM];  // x @ W1
__device__ float g_H [(size_t)N_MAX * HID_DIM];  // spmm1 out (+b1)
__device__ float g_S2[(size_t)N_MAX * OUT_DIM];  // relu(H) @ W2

// CSR scratch
__device__ int  g_rowptr[N_MAX + 1];
__device__ int  g_rowaux[N_MAX];      // counts, then scatter cursors
__device__ int2 g_edges [E_MAX];      // {colidx, weight-as-int}

// ---------------------------------------------------------------------------
__device__ __forceinline__ float to_tf32_rn(float f) {
    uint32_t o;
    asm("cvt.rn.tf32.f32 %0, %1;" : "=r"(o) : "f"(f));
    return __uint_as_float(o);
}

// ---------------------------------------------------------------------------
// GEMM1: C[M,128] = A[M,512] @ W[512,128] via mma.sync.m16n8k8 tf32.
// Block tile 128x128, BK=32. 8 warps (4 along M x 2 along N), warp tile 32x64.
// ---------------------------------------------------------------------------
__global__ __launch_bounds__(256) void gemm1_mma_tf32(
        const float* __restrict__ A, const float* __restrict__ W,
        float* __restrict__ C, int M) {
    constexpr int BM = 128, BN = 128, BK = 32, LDA = 36;
    __shared__ float sA[BM * LDA];   // row-major [m][k], padded
    __shared__ float sB[BN * LDA];   // TRANSPOSED [n][k], padded

    const int tid  = threadIdx.x;
    const int wid  = tid >> 5;
    const int lane = tid & 31;
    const int gid  = lane >> 2;      // 0..7
    const int tig  = lane & 3;       // 0..3
    const int warpM = (wid & 3) * 32;
    const int warpN = (wid >> 2) * 64;
    const int rowBase = blockIdx.x * BM;

    float acc[2][8][4];
    #pragma unroll
    for (int a = 0; a < 2; a++)
        #pragma unroll
        for (int b = 0; b < 8; b++)
            #pragma unroll
            for (int c = 0; c < 4; c++) acc[a][b][c] = 0.f;

    for (int k0 = 0; k0 < IN_DIM; k0 += BK) {
        // A tile: 128 x 32 floats (rn-rounded to tf32)
        #pragma unroll
        for (int i = 0; i < 4; i++) {
            int f = tid + i * 256;
            int r = f >> 3, q = f & 7;
            int m = rowBase + r;
            float4 v = make_float4(0.f, 0.f, 0.f, 0.f);
            if (m < M) v = *(const float4*)(A + (size_t)m * IN_DIM + k0 + q * 4);
            v.x = to_tf32_rn(v.x); v.y = to_tf32_rn(v.y);
            v.z = to_tf32_rn(v.z); v.w = to_tf32_rn(v.w);
            *(float4*)&sA[r * LDA + q * 4] = v;
        }
        // B tile transposed: sB[n][kl] = W[k0+kl][n]
        #pragma unroll
        for (int i = 0; i < 16; i++) {
            int f = tid + i * 256;
            int kl = f >> 7, n = f & (BN - 1);
            sB[n * LDA + kl] = to_tf32_rn(W[(size_t)(k0 + kl) * BN + n]);
        }
        __syncthreads();

        #pragma unroll
        for (int kk = 0; kk < 4; kk++) {
            const int k = kk * 8;
            uint32_t bf[8][2];
            #pragma unroll
            for (int nt = 0; nt < 8; nt++) {
                int n = warpN + nt * 8 + gid;
                bf[nt][0] = __float_as_uint(sB[n * LDA + k + tig]);
                bf[nt][1] = __float_as_uint(sB[n * LDA + k + 4 + tig]);
            }
            #pragma unroll
            for (int mt = 0; mt < 2; mt++) {
                int r0 = warpM + mt * 16 + gid;
                uint32_t a0 = __float_as_uint(sA[r0 * LDA + k + tig]);
                uint32_t a1 = __float_as_uint(sA[(r0 + 8) * LDA + k + tig]);
                uint32_t a2 = __float_as_uint(sA[r0 * LDA + k + 4 + tig]);
                uint32_t a3 = __float_as_uint(sA[(r0 + 8) * LDA + k + 4 + tig]);
                #pragma unroll
                for (int nt = 0; nt < 8; nt++) {
                    asm volatile(
                        "mma.sync.aligned.m16n8k8.row.col.f32.tf32.tf32.f32 "
                        "{%0,%1,%2,%3}, {%4,%5,%6,%7}, {%8,%9}, {%0,%1,%2,%3};"
                        : "+f"(acc[mt][nt][0]), "+f"(acc[mt][nt][1]),
                          "+f"(acc[mt][nt][2]), "+f"(acc[mt][nt][3])
                        : "r"(a0), "r"(a1), "r"(a2), "r"(a3),
                          "r"(bf[nt][0]), "r"(bf[nt][1]));
                }
            }
        }
        __syncthreads();
    }

    #pragma unroll
    for (int mt = 0; mt < 2; mt++) {
        #pragma unroll
        for (int rr = 0; rr < 2; rr++) {
            int m = rowBase + warpM + mt * 16 + rr * 8 + gid;
            if (m < M) {
                float* cp = C + (size_t)m * BN + warpN;
                #pragma unroll
                for (int nt = 0; nt < 8; nt++) {
                    *(float2*)(cp + nt * 8 + 2 * tig) =
                        make_float2(acc[mt][nt][rr * 2 + 0], acc[mt][nt][rr * 2 + 1]);
                }
            }
        }
    }
}

// ---------------------------------------------------------------------------
// fp32 SGEMM for layer 2 (ReLU fused on A load).
// ---------------------------------------------------------------------------
template<int BM, int BN, int BK, bool RELU>
__global__ void sgemm_kernel(const float* __restrict__ A,
                             const float* __restrict__ B,
                             float* __restrict__ C, int M, int K) {
    constexpr int THREADS = (BM / 8) * (BN / 8);
    __shared__ float Ast[BK][BM];
    __shared__ float Bs[BK][BN];

    const int tid  = threadIdx.x;
    const int tcol = tid % (BN / 8);
    const int trow = tid / (BN / 8);
    const int rowBase = blockIdx.x * BM;

    float acc[8][8];
    #pragma unroll
    for (int i = 0; i < 8; i++)
        #pragma unroll
        for (int j = 0; j < 8; j++) acc[i][j] = 0.f;

    for (int k0 = 0; k0 < K; k0 += BK) {
        constexpr int A4 = BM * BK / 4;
        #pragma unroll
        for (int f = tid; f < A4; f += THREADS) {
            int r  = f / (BK / 4);
            int kq = f % (BK / 4);
            int grow = rowBase + r;
            float4 v = make_float4(0.f, 0.f, 0.f, 0.f);
            if (grow < M)
                v = *(const float4*)(A + (size_t)grow * K + k0 + kq * 4);
            if (RELU) {
                v.x = fmaxf(v.x, 0.f); v.y = fmaxf(v.y, 0.f);
                v.z = fmaxf(v.z, 0.f); v.w = fmaxf(v.w, 0.f);
            }
            Ast[kq * 4 + 0][r] = v.x;
            Ast[kq * 4 + 1][r] = v.y;
            Ast[kq * 4 + 2][r] = v.z;
            Ast[kq * 4 + 3][r] = v.w;
        }
        constexpr int B4 = BK * BN / 4;
        #pragma unroll
        for (int f = tid; f < B4; f += THREADS) {
            int kk = f / (BN / 4);
            int c4 = f % (BN / 4);
            *(float4*)&Bs[kk][c4 * 4] =
                *(const float4*)(B + (size_t)(k0 + kk) * BN + c4 * 4);
        }
        __syncthreads();

        #pragma unroll
        for (int kk = 0; kk < BK; kk++) {
            float4 a0 = *(const float4*)&Ast[kk][trow * 8];
            float4 a1 = *(const float4*)&Ast[kk][trow * 8 + 4];
            float4 b0 = *(const float4*)&Bs[kk][tcol * 8];
            float4 b1 = *(const float4*)&Bs[kk][tcol * 8 + 4];
            float a[8] = {a0.x, a0.y, a0.z, a0.w, a1.x, a1.y, a1.z, a1.w};
            float b[8] = {b0.x, b0.y, b0.z, b0.w, b1.x, b1.y, b1.z, b1.w};
            #pragma unroll
            for (int i = 0; i < 8; i++)
                #pragma unroll
                for (int j = 0; j < 8; j++)
                    acc[i][j] = fmaf(a[i], b[j], acc[i][j]);
        }
        __syncthreads();
    }

    #pragma unroll
    for (int i = 0; i < 8; i++) {
        int grow = rowBase + trow * 8 + i;
        if (grow < M) {
            float* cp = C + (size_t)grow * BN + tcol * 8;
            *(float4*)cp       = make_float4(acc[i][0], acc[i][1], acc[i][2], acc[i][3]);
            *(float4*)(cp + 4) = make_float4(acc[i][4], acc[i][5], acc[i][6], acc[i][7]);
        }
    }
}

// ---------------------------------------------------------------------------
// CSR build
// ---------------------------------------------------------------------------
__global__ void zero_counts_kernel(int* __restrict__ cnt, int n) {
    int i = blockIdx.x * blockDim.x + threadIdx.x;
    if (i < n) cnt[i] = 0;
}

__global__ void hist_kernel(const int* __restrict__ rows, int* __restrict__ cnt, int E) {
    int e = blockIdx.x * blockDim.x + threadIdx.x;
    if (e < E) atomicAdd(&cnt[rows[e]], 1);
}

// Single-block exclusive scan over N counts (chunk-per-thread + block scan).
__global__ __launch_bounds__(1024) void scan_kernel(
        int* __restrict__ cnt_and_cursor,   // in: counts, out: cursors (=offsets)
        int* __restrict__ rowptr, int N, int E) {
    __shared__ int part[1024];
    const int t = threadIdx.x;
    const int chunk = (N + 1023) / 1024;
    const int lo = t * chunk;
    const int hi = min(lo + chunk, N);
    int s = 0;
    for (int i = lo; i < hi; i++) s += cnt_and_cursor[i];
    part[t] = s;
    __syncthreads();
    #pragma unroll
    for (int off = 1; off < 1024; off <<= 1) {
        int v = (t >= off) ? part[t - off] : 0;
        __syncthreads();
        part[t] += v;
        __syncthreads();
    }
    int base = (t == 0) ? 0 : part[t - 1];
    for (int i = lo; i < hi; i++) {
        int c = cnt_and_cursor[i];
        rowptr[i] = base;
        cnt_and_cursor[i] = base;   // scatter cursor
        base += c;
    }
    if (t == 0) rowptr[N] = E;
}

__global__ void scatter_kernel(const int* __restrict__ rows,
                               const int* __restrict__ cols,
                               const float* __restrict__ ew,
                               int* __restrict__ cursor,
                               int2* __restrict__ edges, int E) {
    int e = blockIdx.x * blockDim.x + threadIdx.x;
    if (e >= E) return;
    int r = rows[e];
    int pos = atomicAdd(&cursor[r], 1);
    edges[pos] = make_int2(cols[e], __float_as_int(ew[e]));
}

// ---------------------------------------------------------------------------
// CSR SpMM: warp per row, VEC floats per lane (D = 32*VEC).
// dst[row] = bias + sum_j w[j] * src[col[j]]
// ---------------------------------------------------------------------------
template<int VEC>
__global__ void csr_spmm_kernel(const int* __restrict__ rowptr,
                                const int2* __restrict__ edges,
                                const float* __restrict__ src,
                                const float* __restrict__ bias,
                                float* __restrict__ dst, int N) {
    constexpr int D = VEC * 32;
    const int lane = threadIdx.x & 31;
    const int row  = blockIdx.x * (blockDim.x >> 5) + (threadIdx.x >> 5);
    if (row >= N) return;

    const int s = rowptr[row];
    const int e = rowptr[row + 1];

    float acc[VEC];
    #pragma unroll
    for (int v = 0; v < VEC; v++) acc[v] = bias[lane * VEC + v];

    int j = s;
    for (; j + 2 <= e; j += 2) {
        int2 e0 = edges[j], e1 = edges[j + 1];
        float w0 = __int_as_float(e0.y), w1 = __int_as_float(e1.y);
        const float* p0 = src + (size_t)e0.x * D + lane * VEC;
        const float* p1 = src + (size_t)e1.x * D + lane * VEC;
        if (VEC == 4) {
            float4 v0 = *(const float4*)p0;
            float4 v1 = *(const float4*)p1;
            acc[0] = fmaf(w0, v0.x, fmaf(w1, v1.x, acc[0]));
            acc[1] = fmaf(w0, v0.y, fmaf(w1, v1.y, acc[1]));
            acc[2] = fmaf(w0, v0.z, fmaf(w1, v1.z, acc[2]));
            acc[3] = fmaf(w0, v0.w, fmaf(w1, v1.w, acc[3]));
        } else {
            float2 v0 = *(const float2*)p0;
            float2 v1 = *(const float2*)p1;
            acc[0] = fmaf(w0, v0.x, fmaf(w1, v1.x, acc[0]));
            acc[1] = fmaf(w0, v0.y, fmaf(w1, v1.y, acc[1]));
        }
    }
    if (j < e) {
        int2 e0 = edges[j];
        float w0 = __int_as_float(e0.y);
        const float* p0 = src + (size_t)e0.x * D + lane * VEC;
        if (VEC == 4) {
            float4 v0 = *(const float4*)p0;
            acc[0] = fmaf(w0, v0.x, acc[0]);
            acc[1] = fmaf(w0, v0.y, acc[1]);
            acc[2] = fmaf(w0, v0.z, acc[2]);
            acc[3] = fmaf(w0, v0.w, acc[3]);
        } else {
            float2 v0 = *(const float2*)p0;
            acc[0] = fmaf(w0, v0.x, acc[0]);
            acc[1] = fmaf(w0, v0.y, acc[1]);
        }
    }

    float* dp = dst + (size_t)row * D + lane * VEC;
    if (VEC == 4)
        *(float4*)dp = make_float4(acc[0], acc[1], acc[2], acc[3]);
    else
        *(float2*)dp = make_float2(acc[0], acc[1]);
}

// ---------------------------------------------------------------------------
extern "C" void kernel_launch(void* const* d_in, const int* in_sizes, int n_in,
                              void* d_out, int out_size) {
    const float* x  = (const float*)d_in[0];
    const int*   ei = (const int*)d_in[1];     // [2, E] int32
    const float* ew = (const float*)d_in[2];
    const float* W1 = (const float*)d_in[3];
    const float* b1 = (const float*)d_in[4];
    const float* W2 = (const float*)d_in[5];
    const float* b2 = (const float*)d_in[6];
    float* out = (float*)d_out;

    const int M = in_sizes[0] / IN_DIM;   // 50000
    const int E = in_sizes[2];            // 1600000

    float *S1, *H, *S2;
    int *rowptr, *rowaux;
    int2 *edges;
    cudaGetSymbolAddress((void**)&S1, g_S1);
    cudaGetSymbolAddress((void**)&H,  g_H);
    cudaGetSymbolAddress((void**)&S2, g_S2);
    cudaGetSymbolAddress((void**)&rowptr, g_rowptr);
    cudaGetSymbolAddress((void**)&rowaux, g_rowaux);
    cudaGetSymbolAddress((void**)&edges,  g_edges);

    const int* e_rows = ei;
    const int* e_cols = ei + E;

    // --- CSR build (shared by both spmms) ---
    zero_counts_kernel<<<(M + 255) / 256, 256>>>(rowaux, M);
    hist_kernel<<<(E + 255) / 256, 256>>>(e_rows, rowaux, E);
    scan_kernel<<<1, 1024>>>(rowaux, rowptr, M, E);
    scatter_kernel<<<(E + 255) / 256, 256>>>(e_rows, e_cols, ew, rowaux, edges, E);

    // --- GEMM1: S1 = x @ W1 (tf32 mma) ---
    gemm1_mma_tf32<<<(M + 127) / 128, 256>>>(x, W1, S1, M);

    // --- SpMM1: H = A @ S1 + b1 ---
    csr_spmm_kernel<4><<<(M + 7) / 8, 256>>>(rowptr, edges, S1, b1, H, M);

    // --- GEMM2: S2 = relu(H) @ W2 (fp32 FFMA) ---
    sgemm_kernel<128, OUT_DIM, 16, true>
        <<<(M + 127) / 128, (128 / 8) * (OUT_DIM / 8)>>>(H, W2, S2, M, HID_DIM);

    // --- SpMM2: out = A @ S2 + b2 ---
    csr_spmm_kernel<2><<<(M + 7) / 8, 256>>>(rowptr, edges, S2, b2, out, M);
}